// round 3
// baseline (speedup 1.0000x reference)
#include <cuda_runtime.h>
#include <cstdint>

#define N_NODES 100000
#define N_EDGES 1600000
#define D 64
#define CAP 64            // per-node incoming-edge bucket capacity (Poisson(16), max ~45)

// Scratch (__device__ globals: allocation-free per harness rules)
__device__ int   g_is64;                          // 1 if edge_index is int64, 0 if int32
__device__ float g_deg[N_NODES];                  // degree, then dinv in place
__device__ int   g_cnt[N_NODES];                  // bucket fill counters
__device__ int2  g_bucket[(size_t)N_NODES * CAP]; // {row, bitcast(norm)}
__device__ __align__(16) float g_tx1[(size_t)N_NODES * D];

// ---------------------------------------------------------------------------
// K0: detect edge_index dtype. int64 little-endian non-negative values have
// zero high words at every odd int32 position; int32 index data does not.
// ---------------------------------------------------------------------------
__global__ void detect_kernel(const int* __restrict__ ei) {
    __shared__ int any;
    if (threadIdx.x == 0) any = 0;
    __syncthreads();
    for (int i = 1 + 2 * threadIdx.x; i < 4096; i += 2 * blockDim.x)
        if (ei[i] != 0) atomicOr(&any, 1);
    __syncthreads();
    if (threadIdx.x == 0) g_is64 = any ? 0 : 1;
}

__device__ __forceinline__ void load_edge(const void* ei, int E, int e,
                                          int& r, int& c) {
    if (g_is64) {
        const long long* p = (const long long*)ei;
        r = (int)p[e];
        c = (int)p[(size_t)E + e];
    } else {
        const int* p = (const int*)ei;
        r = p[e];
        c = p[E + e];
    }
}

// ---------------------------------------------------------------------------
// K1: zero deg + counters + Tx1
// ---------------------------------------------------------------------------
__global__ void zero_kernel() {
    int i = blockIdx.x * blockDim.x + threadIdx.x;
    if (i < N_NODES) { g_deg[i] = 0.f; g_cnt[i] = 0; }
    int n4 = N_NODES * (D / 4);
    if (i < n4) ((float4*)g_tx1)[i] = make_float4(0.f, 0.f, 0.f, 0.f);
}

// ---------------------------------------------------------------------------
// K2: deg[row] += w
// ---------------------------------------------------------------------------
__global__ void deg_kernel(const void* __restrict__ ei,
                           const float* __restrict__ ew, int E) {
    int e = blockIdx.x * blockDim.x + threadIdx.x;
    if (e < E) {
        int r, c;
        load_edge(ei, E, e, r, c);
        atomicAdd(&g_deg[r], __ldg(&ew[e]));
    }
}

// ---------------------------------------------------------------------------
// K3: deg -> dinv (in place)
// ---------------------------------------------------------------------------
__global__ void dinv_kernel() {
    int i = blockIdx.x * blockDim.x + threadIdx.x;
    if (i < N_NODES) {
        float d = g_deg[i];
        g_deg[i] = (d > 0.f) ? rsqrtf(d) : 0.f;
    }
}

// ---------------------------------------------------------------------------
// K4: bucket fill. norm = -dinv[row]*w*dinv[col]; append {row,norm} to
// col's bucket. Overflow fallback: scalar atomics straight into g_tx1.
// ---------------------------------------------------------------------------
__global__ void fill_kernel(const void* __restrict__ ei,
                            const float* __restrict__ ew,
                            const float* __restrict__ x, int E) {
    int e = blockIdx.x * blockDim.x + threadIdx.x;
    if (e >= E) return;
    int r, c;
    load_edge(ei, E, e, r, c);
    float w = __ldg(&ew[e]);
    float norm = -g_deg[r] * w * g_deg[c];   // g_deg holds dinv now
    int pos = atomicAdd(&g_cnt[c], 1);
    if (pos < CAP) {
        g_bucket[(size_t)c * CAP + pos] = make_int2(r, __float_as_int(norm));
    } else {
        // statistically never taken; correctness insurance
        const float* xr = x + (size_t)r * D;
        float* t = g_tx1 + (size_t)c * D;
        for (int j = 0; j < D; j++) atomicAdd(&t[j], norm * __ldg(&xr[j]));
    }
}

// ---------------------------------------------------------------------------
// K5: gather. One warp per destination node; lanes own columns lane, lane+32.
// ---------------------------------------------------------------------------
__global__ void __launch_bounds__(256)
gather_kernel(const float* __restrict__ x) {
    int warp_in_block = threadIdx.x >> 5;
    int lane = threadIdx.x & 31;
    int node = blockIdx.x * (blockDim.x >> 5) + warp_in_block;
    if (node >= N_NODES) return;

    int n = g_cnt[node];
    if (n > CAP) n = CAP;

    float a0 = 0.f, a1 = 0.f;
    const int2* bk = &g_bucket[(size_t)node * CAP];

    for (int base = 0; base < n; base += 32) {
        int m = n - base; if (m > 32) m = 32;
        int2 ed = make_int2(0, 0);
        if (lane < m) ed = bk[base + lane];
        #pragma unroll 4
        for (int j = 0; j < m; j++) {
            int   r  = __shfl_sync(0xffffffffu, ed.x, j);
            float nm = __int_as_float(__shfl_sync(0xffffffffu, ed.y, j));
            const float* xr = x + (size_t)r * D;
            a0 = fmaf(nm, __ldg(xr + lane),      a0);
            a1 = fmaf(nm, __ldg(xr + 32 + lane), a1);
        }
    }
    float* t = g_tx1 + (size_t)node * D;
    t[lane]      += a0;   // += to keep overflow-fallback contributions
    t[lane + 32] += a1;
}

// ---------------------------------------------------------------------------
// K6: out = x @ W0 + Tx1 @ W1 + b.  One thread per node row.
// ---------------------------------------------------------------------------
__global__ void __launch_bounds__(256)
gemm_kernel(const float* __restrict__ x,
            const float* __restrict__ W0,
            const float* __restrict__ W1,
            const float* __restrict__ b,
            float* __restrict__ out, int N) {
    __shared__ __align__(16) float sW0[D * D];
    __shared__ __align__(16) float sW1[D * D];
    __shared__ __align__(16) float sb[D];

    for (int i = threadIdx.x; i < D * D; i += blockDim.x) {
        sW0[i] = W0[i];
        sW1[i] = W1[i];
    }
    if (threadIdx.x < D) sb[threadIdx.x] = b[threadIdx.x];
    __syncthreads();

    int row = blockIdx.x * blockDim.x + threadIdx.x;
    if (row >= N) return;

    float4 acc[D / 4];
#pragma unroll
    for (int j = 0; j < D / 4; j++)
        acc[j] = ((const float4*)sb)[j];

    const float4* xr = (const float4*)(x + (size_t)row * D);
    const float4* tr = (const float4*)(g_tx1 + (size_t)row * D);

#pragma unroll
    for (int k4 = 0; k4 < D / 4; k4++) {
        float4 xv = __ldg(&xr[k4]);
        float4 tv = tr[k4];
#pragma unroll
        for (int kk = 0; kk < 4; kk++) {
            int k = k4 * 4 + kk;
            float xs = (&xv.x)[kk];
            float ts = (&tv.x)[kk];
            const float4* w0r = (const float4*)&sW0[k * D];
            const float4* w1r = (const float4*)&sW1[k * D];
#pragma unroll
            for (int j = 0; j < D / 4; j++) {
                float4 w0 = w0r[j];
                float4 w1 = w1r[j];
                acc[j].x = fmaf(xs, w0.x, fmaf(ts, w1.x, acc[j].x));
                acc[j].y = fmaf(xs, w0.y, fmaf(ts, w1.y, acc[j].y));
                acc[j].z = fmaf(xs, w0.z, fmaf(ts, w1.z, acc[j].z));
                acc[j].w = fmaf(xs, w0.w, fmaf(ts, w1.w, acc[j].w));
            }
        }
    }

    float4* o = (float4*)(out + (size_t)row * D);
#pragma unroll
    for (int j = 0; j < D / 4; j++) o[j] = acc[j];
}

// ---------------------------------------------------------------------------
// Launch
// ---------------------------------------------------------------------------
extern "C" void kernel_launch(void* const* d_in, const int* in_sizes, int n_in,
                              void* d_out, int out_size) {
    const float* x  = (const float*)d_in[0];
    const void*  ei = d_in[1];
    const float* ew = (const float*)d_in[2];
    const float* W0 = (const float*)d_in[3];
    const float* W1 = (const float*)d_in[4];
    const float* b  = (const float*)d_in[5];
    float*       out = (float*)d_out;

    int E = in_sizes[2];
    int N = in_sizes[0] / D;

    detect_kernel<<<1, 256>>>((const int*)ei);
    {
        int n = N_NODES * (D / 4);   // largest of the zeroed ranges
        zero_kernel<<<(n + 255) / 256, 256>>>();
    }
    deg_kernel<<<(E + 255) / 256, 256>>>(ei, ew, E);
    dinv_kernel<<<(N_NODES + 255) / 256, 256>>>();
    fill_kernel<<<(E + 255) / 256, 256>>>(ei, ew, x, E);
    {
        int warps_per_block = 256 / 32;
        int blocks = (N_NODES + warps_per_block - 1) / warps_per_block;
        gather_kernel<<<blocks, 256>>>(x);
    }
    gemm_kernel<<<(N + 255) / 256, 256>>>(x, W0, W1, b, out, N);
}

// round 4
// speedup vs baseline: 1.0471x; 1.0471x over previous
#include <cuda_runtime.h>
#include <cstdint>

#define N_NODES 100000
#define N_EDGES 1600000
#define D 64
#define CAP 64            // per-node in-edge bucket capacity (Poisson(16), max ~45)
#define OVF_CAP 8192      // overflow edge list (statistically never used)

// Scratch (__device__ globals: allocation-free per harness rules)
__device__ int   g_is64;                          // edge_index dtype flag
__device__ float g_deg[N_NODES];                  // degree, then dinv in place
__device__ int   g_cnt[N_NODES];                  // bucket fill counters
__device__ int2  g_bucket[(size_t)N_NODES * CAP]; // {row, bitcast(w)}
__device__ int   g_ovf_cnt;
__device__ int   g_ovf[OVF_CAP];                  // overflow edge ids
__device__ __align__(16) float g_tx1[(size_t)N_NODES * D];

// ---------------------------------------------------------------------------
// K0: detect edge_index dtype (int64 => odd int32 words are all zero).
// ---------------------------------------------------------------------------
__global__ void detect_kernel(const int* __restrict__ ei) {
    __shared__ int any;
    if (threadIdx.x == 0) any = 0;
    __syncthreads();
    for (int i = 1 + 2 * threadIdx.x; i < 4096; i += 2 * blockDim.x)
        if (ei[i] != 0) atomicOr(&any, 1);
    __syncthreads();
    if (threadIdx.x == 0) g_is64 = any ? 0 : 1;
}

__device__ __forceinline__ void load_edge(const void* ei, int E, int e,
                                          int& r, int& c) {
    if (g_is64) {
        const long long* p = (const long long*)ei;
        r = (int)p[e];
        c = (int)p[(size_t)E + e];
    } else {
        const int* p = (const int*)ei;
        r = p[e];
        c = p[E + e];
    }
}

// ---------------------------------------------------------------------------
// K1: zero deg + counters (tx1 no longer needs zeroing)
// ---------------------------------------------------------------------------
__global__ void zero_kernel() {
    int i = blockIdx.x * blockDim.x + threadIdx.x;
    if (i < N_NODES) { g_deg[i] = 0.f; g_cnt[i] = 0; }
    if (i == 0) g_ovf_cnt = 0;
}

// ---------------------------------------------------------------------------
// K2: single edge pass — deg[row] += w AND append {row, w} to col's bucket.
// ---------------------------------------------------------------------------
__global__ void edge_pass_kernel(const void* __restrict__ ei,
                                 const float* __restrict__ ew, int E) {
    int e = blockIdx.x * blockDim.x + threadIdx.x;
    if (e >= E) return;
    int r, c;
    load_edge(ei, E, e, r, c);
    float w = __ldg(&ew[e]);
    atomicAdd(&g_deg[r], w);
    int pos = atomicAdd(&g_cnt[c], 1);
    if (pos < CAP) {
        g_bucket[(size_t)c * CAP + pos] = make_int2(r, __float_as_int(w));
    } else {
        int o = atomicAdd(&g_ovf_cnt, 1);
        if (o < OVF_CAP) g_ovf[o] = e;
    }
}

// ---------------------------------------------------------------------------
// K3: deg -> dinv (in place)
// ---------------------------------------------------------------------------
__global__ void dinv_kernel() {
    int i = blockIdx.x * blockDim.x + threadIdx.x;
    if (i < N_NODES) {
        float d = g_deg[i];
        g_deg[i] = (d > 0.f) ? rsqrtf(d) : 0.f;
    }
}

// ---------------------------------------------------------------------------
// K4: gather. One warp per destination node; lanes own columns lane, lane+32.
// norm computed inline: -dinv[row] * w * dinv[col].
// ---------------------------------------------------------------------------
__global__ void __launch_bounds__(256)
gather_kernel(const float* __restrict__ x) {
    int warp_in_block = threadIdx.x >> 5;
    int lane = threadIdx.x & 31;
    int node = blockIdx.x * (blockDim.x >> 5) + warp_in_block;
    if (node >= N_NODES) return;

    int n = g_cnt[node];
    if (n > CAP) n = CAP;
    float dinv_c = g_deg[node];          // holds dinv now

    float a0 = 0.f, a1 = 0.f;
    const int2* bk = &g_bucket[(size_t)node * CAP];

    for (int base = 0; base < n; base += 32) {
        int m = n - base; if (m > 32) m = 32;
        int   r_l  = 0;
        float nm_l = 0.f;
        if (lane < m) {
            int2 ed = bk[base + lane];
            r_l  = ed.x;
            nm_l = -g_deg[ed.x] * __int_as_float(ed.y) * dinv_c;
        }
        #pragma unroll 4
        for (int j = 0; j < m; j++) {
            int   r  = __shfl_sync(0xffffffffu, r_l, j);
            float nm = __shfl_sync(0xffffffffu, nm_l, j);
            const float* xr = x + (size_t)r * D;
            a0 = fmaf(nm, __ldg(xr + lane),      a0);
            a1 = fmaf(nm, __ldg(xr + 32 + lane), a1);
        }
    }
    float* t = g_tx1 + (size_t)node * D;
    t[lane]      = a0;
    t[lane + 32] = a1;
}

// ---------------------------------------------------------------------------
// K5: overflow drain (statistically empty). One thread per overflow slot.
// ---------------------------------------------------------------------------
__global__ void overflow_kernel(const void* __restrict__ ei,
                                const float* __restrict__ ew,
                                const float* __restrict__ x, int E) {
    int i = blockIdx.x * blockDim.x + threadIdx.x;
    int cnt = g_ovf_cnt;
    if (cnt > OVF_CAP) cnt = OVF_CAP;
    if (i >= cnt) return;
    int e = g_ovf[i];
    int r, c;
    load_edge(ei, E, e, r, c);
    float w = __ldg(&ew[e]);
    float norm = -g_deg[r] * w * g_deg[c];
    const float* xr = x + (size_t)r * D;
    float* t = g_tx1 + (size_t)c * D;
    for (int j = 0; j < D; j++) atomicAdd(&t[j], norm * __ldg(&xr[j]));
}

// ---------------------------------------------------------------------------
// K6: out = x @ W0 + Tx1 @ W1 + b.  One thread per node row.
// ---------------------------------------------------------------------------
__global__ void __launch_bounds__(256)
gemm_kernel(const float* __restrict__ x,
            const float* __restrict__ W0,
            const float* __restrict__ W1,
            const float* __restrict__ b,
            float* __restrict__ out, int N) {
    __shared__ __align__(16) float sW0[D * D];
    __shared__ __align__(16) float sW1[D * D];
    __shared__ __align__(16) float sb[D];

    for (int i = threadIdx.x; i < D * D; i += blockDim.x) {
        sW0[i] = W0[i];
        sW1[i] = W1[i];
    }
    if (threadIdx.x < D) sb[threadIdx.x] = b[threadIdx.x];
    __syncthreads();

    int row = blockIdx.x * blockDim.x + threadIdx.x;
    if (row >= N) return;

    float4 acc[D / 4];
#pragma unroll
    for (int j = 0; j < D / 4; j++)
        acc[j] = ((const float4*)sb)[j];

    const float4* xr = (const float4*)(x + (size_t)row * D);
    const float4* tr = (const float4*)(g_tx1 + (size_t)row * D);

#pragma unroll
    for (int k4 = 0; k4 < D / 4; k4++) {
        float4 xv = __ldg(&xr[k4]);
        float4 tv = tr[k4];
#pragma unroll
        for (int kk = 0; kk < 4; kk++) {
            int k = k4 * 4 + kk;
            float xs = (&xv.x)[kk];
            float ts = (&tv.x)[kk];
            const float4* w0r = (const float4*)&sW0[k * D];
            const float4* w1r = (const float4*)&sW1[k * D];
#pragma unroll
            for (int j = 0; j < D / 4; j++) {
                float4 w0 = w0r[j];
                float4 w1 = w1r[j];
                acc[j].x = fmaf(xs, w0.x, fmaf(ts, w1.x, acc[j].x));
                acc[j].y = fmaf(xs, w0.y, fmaf(ts, w1.y, acc[j].y));
                acc[j].z = fmaf(xs, w0.z, fmaf(ts, w1.z, acc[j].z));
                acc[j].w = fmaf(xs, w0.w, fmaf(ts, w1.w, acc[j].w));
            }
        }
    }

    float4* o = (float4*)(out + (size_t)row * D);
#pragma unroll
    for (int j = 0; j < D / 4; j++) o[j] = acc[j];
}

// ---------------------------------------------------------------------------
// Launch
// ---------------------------------------------------------------------------
extern "C" void kernel_launch(void* const* d_in, const int* in_sizes, int n_in,
                              void* d_out, int out_size) {
    const float* x  = (const float*)d_in[0];
    const void*  ei = d_in[1];
    const float* ew = (const float*)d_in[2];
    const float* W0 = (const float*)d_in[3];
    const float* W1 = (const float*)d_in[4];
    const float* b  = (const float*)d_in[5];
    float*       out = (float*)d_out;

    int E = in_sizes[2];
    int N = in_sizes[0] / D;

    detect_kernel<<<1, 256>>>((const int*)ei);
    zero_kernel<<<(N_NODES + 255) / 256, 256>>>();
    edge_pass_kernel<<<(E + 255) / 256, 256>>>(ei, ew, E);
    dinv_kernel<<<(N_NODES + 255) / 256, 256>>>();
    {
        int warps_per_block = 256 / 32;
        int blocks = (N_NODES + warps_per_block - 1) / warps_per_block;
        gather_kernel<<<blocks, 256>>>(x);
    }
    overflow_kernel<<<(OVF_CAP + 255) / 256, 256>>>(ei, ew, x, E);
    gemm_kernel<<<(N + 255) / 256, 256>>>(x, W0, W1, b, out, N);
}